// round 3
// baseline (speedup 1.0000x reference)
#include <cuda_runtime.h>
#include <cuda_bf16.h>
#include <math.h>

// ---------------- problem constants ----------------
#define Vv 32000
#define Dd 1024
#define NLAYER 4
#define ED 2048
#define Nn 16
#define DR 64
#define DCONV 4
#define Bb 2
#define Ll 1024
#define Mm (Bb * Ll)      // 2048 tokens
#define DX (DR + 2 * Nn)  // 96

// ---------------- scratch (no allocs allowed) ----------------
__device__ __align__(256) float g_x[Mm * Dd];
__device__ __align__(256) float g_xn[Mm * Dd];
__device__ __align__(256) float g_xz[Mm * 2 * ED];
__device__ __align__(256) float g_xs[Mm * ED];
__device__ __align__(256) float g_y[Mm * ED];
__device__ __align__(256) float g_delta[Mm * ED];
__device__ __align__(256) float g_dbc[Mm * DX];

// ---------------- embedding gather ----------------
__global__ void __launch_bounds__(256) embed_kernel(const int* __restrict__ tok,
                                                    const float* __restrict__ emb,
                                                    float* __restrict__ out) {
    int idx = blockIdx.x * 256 + threadIdx.x;   // over Mm*Dd
    int m = idx >> 10;
    int d = idx & 1023;
    out[idx] = emb[(size_t)tok[m] * Dd + d];
}

// ---------------- rmsnorm (block per row, D=1024) ----------------
__global__ void __launch_bounds__(256) rmsnorm_kernel(const float* __restrict__ x,
                                                      const float* __restrict__ w,
                                                      float* __restrict__ out) {
    int row = blockIdx.x;
    const float* xr = x + (size_t)row * Dd;
    float v[4];
    float s = 0.f;
#pragma unroll
    for (int i = 0; i < 4; i++) {
        v[i] = xr[threadIdx.x + i * 256];
        s += v[i] * v[i];
    }
#pragma unroll
    for (int o = 16; o; o >>= 1) s += __shfl_xor_sync(0xffffffffu, s, o);
    __shared__ float ss[8];
    if ((threadIdx.x & 31) == 0) ss[threadIdx.x >> 5] = s;
    __syncthreads();
    if (threadIdx.x < 32) {
        float t = (threadIdx.x < 8) ? ss[threadIdx.x] : 0.f;
#pragma unroll
        for (int o = 4; o; o >>= 1) t += __shfl_xor_sync(0xffffffffu, t, o);
        if (threadIdx.x == 0) ss[0] = t;
    }
    __syncthreads();
    float r = rsqrtf(ss[0] * (1.f / (float)Dd) + 1e-5f);
    float* orow = out + (size_t)row * Dd;
#pragma unroll
    for (int i = 0; i < 4; i++) {
        int d = threadIdx.x + i * 256;
        orow[d] = v[i] * r * w[d];
    }
}

// ---------------- depthwise causal conv (DC=4) + bias + silu ----------------
__global__ void __launch_bounds__(256) conv_silu_kernel(const float* __restrict__ xz,
                                                        const float* __restrict__ cw,
                                                        const float* __restrict__ cb,
                                                        float* __restrict__ xs) {
    int idx = blockIdx.x * 256 + threadIdx.x;    // over Mm*ED
    int e = idx & (ED - 1);
    int m = idx >> 11;          // token index b*L+l
    int l = m & (Ll - 1);
    const float* xin = xz + (size_t)m * (2 * ED) + e;   // xin part of xz
    float w0 = cw[e * 4 + 0], w1 = cw[e * 4 + 1], w2 = cw[e * 4 + 2], w3 = cw[e * 4 + 3];
    float acc = cb[e] + w3 * xin[0];
    if (l >= 1) acc += w2 * xin[-(2 * ED)];
    if (l >= 2) acc += w1 * xin[-2 * (2 * ED)];
    if (l >= 3) acc += w0 * xin[-3 * (2 * ED)];
    xs[idx] = acc / (1.f + __expf(-acc));       // silu
}

// ---------------- generic SGEMM: C(M,N) = A(M,K) * B(N,K)^T ----------------
// EPI: 0 = store, 1 = accumulate into C (residual), 2 = softplus(acc + bias[n])
#define BM 64
#define BN 64
#define BKT 16

template <int EPI>
__global__ void __launch_bounds__(256) sgemm_nt(const float* __restrict__ A, int lda,
                                                const float* __restrict__ Bm, int ldb,
                                                float* __restrict__ C, int ldc,
                                                int M, int N, int K,
                                                const float* __restrict__ bias) {
    __shared__ float As[BKT][BM];
    __shared__ float Bs[BKT][BN];
    int tid = threadIdx.x;
    int m0 = blockIdx.y * BM;
    int n0 = blockIdx.x * BN;
    int lrow = tid >> 2;
    int lkv = (tid & 3) << 2;
    int tx = tid & 15;     // n sub-tile
    int ty = tid >> 4;     // m sub-tile
    float acc[4][4] = {};

    for (int k0 = 0; k0 < K; k0 += BKT) {
        float4 av = make_float4(0.f, 0.f, 0.f, 0.f);
        if (m0 + lrow < M)
            av = *(const float4*)(A + (size_t)(m0 + lrow) * lda + k0 + lkv);
        As[lkv + 0][lrow] = av.x;
        As[lkv + 1][lrow] = av.y;
        As[lkv + 2][lrow] = av.z;
        As[lkv + 3][lrow] = av.w;
        float4 bv = make_float4(0.f, 0.f, 0.f, 0.f);
        if (n0 + lrow < N)
            bv = *(const float4*)(Bm + (size_t)(n0 + lrow) * ldb + k0 + lkv);
        Bs[lkv + 0][lrow] = bv.x;
        Bs[lkv + 1][lrow] = bv.y;
        Bs[lkv + 2][lrow] = bv.z;
        Bs[lkv + 3][lrow] = bv.w;
        __syncthreads();
#pragma unroll
        for (int k = 0; k < BKT; k++) {
            float a[4], b[4];
#pragma unroll
            for (int i = 0; i < 4; i++) a[i] = As[k][ty * 4 + i];
#pragma unroll
            for (int j = 0; j < 4; j++) b[j] = Bs[k][tx * 4 + j];
#pragma unroll
            for (int i = 0; i < 4; i++)
#pragma unroll
                for (int j = 0; j < 4; j++) acc[i][j] = fmaf(a[i], b[j], acc[i][j]);
        }
        __syncthreads();
    }

#pragma unroll
    for (int i = 0; i < 4; i++) {
        int m = m0 + ty * 4 + i;
        if (m >= M) continue;
#pragma unroll
        for (int j = 0; j < 4; j++) {
            int n = n0 + tx * 4 + j;
            if (n >= N) continue;
            float v = acc[i][j];
            size_t off = (size_t)m * ldc + n;
            if (EPI == 1) v += C[off];
            if (EPI == 2) {
                v += bias[n];
                v = (v > 20.f) ? v : log1pf(expf(v));   // softplus
            }
            C[off] = v;
        }
    }
}

// ---------------- selective scan ----------------
// 16 lanes per channel (one state n each), h kept in register, serial over t.
// Fuses: dA/dBx on the fly, y = sum_n h*C + D*xs, gate by silu(z), write y.
__global__ void __launch_bounds__(256) scan_kernel(const float* __restrict__ delta,
                                                   const float* __restrict__ xs,
                                                   const float* __restrict__ dbc,
                                                   const float* __restrict__ xz,
                                                   const float* __restrict__ A_log,
                                                   const float* __restrict__ Dp,
                                                   float* __restrict__ y) {
    int ch = blockIdx.x * 16 + (threadIdx.x >> 4);   // 0 .. B*ED-1
    int n = threadIdx.x & 15;
    int b = ch >> 11;          // / ED
    int e = ch & (ED - 1);
    // A = -exp(A_log);  premultiply by log2(e) so dA = exp2f(delta * a2)
    float a2 = -__expf(A_log[e * Nn + n]) * 1.44269504f;
    float dpar = Dp[e];
    float h = 0.f;
    size_t m0 = (size_t)b * Ll;
    const float* pd = delta + m0 * ED + e;
    const float* pxs = xs + m0 * ED + e;
    const float* pB = dbc + m0 * DX + DR + n;
    const float* pC = dbc + m0 * DX + DR + Nn + n;
    const float* pz = xz + m0 * (2 * ED) + ED + e;
    float* py = y + m0 * ED + e;

    for (int t = 0; t < Ll; t++) {
        float d = *pd;
        float xv = *pxs;
        float Bn = *pB;
        float Cn = *pC;
        float da = exp2f(d * a2);
        h = fmaf(da, h, d * xv * Bn);
        float p = h * Cn;
        p += __shfl_xor_sync(0xffffffffu, p, 1);
        p += __shfl_xor_sync(0xffffffffu, p, 2);
        p += __shfl_xor_sync(0xffffffffu, p, 4);
        p += __shfl_xor_sync(0xffffffffu, p, 8);
        if (n == 0) {
            float z = *pz;
            float sz = z / (1.f + __expf(-z));
            py[0] = (p + dpar * xv) * sz;
        }
        pd += ED;
        pxs += ED;
        pB += DX;
        pC += DX;
        pz += 2 * ED;
        py += ED;
    }
}

// ---------------- host side ----------------
static void launch_sgemm(int epi, const float* A, int lda, const float* B, int ldb,
                         float* C, int ldc, int M, int N, int K, const float* bias) {
    dim3 grid((N + BN - 1) / BN, (M + BM - 1) / BM);
    dim3 block(256);
    if (epi == 0)
        sgemm_nt<0><<<grid, block>>>(A, lda, B, ldb, C, ldc, M, N, K, bias);
    else if (epi == 1)
        sgemm_nt<1><<<grid, block>>>(A, lda, B, ldb, C, ldc, M, N, K, bias);
    else
        sgemm_nt<2><<<grid, block>>>(A, lda, B, ldb, C, ldc, M, N, K, bias);
}

extern "C" void kernel_launch(void* const* d_in, const int* in_sizes, int n_in,
                              void* d_out, int out_size) {
    const int* tokens = (const int*)d_in[0];
    const float* embedding = (const float*)d_in[1];
    const float* in_proj_w = (const float*)d_in[2];
    const float* conv_w = (const float*)d_in[3];
    const float* conv_b = (const float*)d_in[4];
    const float* x_proj_w = (const float*)d_in[5];
    const float* dt_proj_w = (const float*)d_in[6];
    const float* dt_proj_b = (const float*)d_in[7];
    const float* A_log = (const float*)d_in[8];
    const float* D_param = (const float*)d_in[9];
    const float* out_proj_w = (const float*)d_in[10];
    const float* norm_w = (const float*)d_in[11];
    const float* norm_f_w = (const float*)d_in[12];
    float* logits = (float*)d_out;

    float *px, *pxn, *pxz, *pxs, *py, *pdelta, *pdbc;
    cudaGetSymbolAddress((void**)&px, g_x);
    cudaGetSymbolAddress((void**)&pxn, g_xn);
    cudaGetSymbolAddress((void**)&pxz, g_xz);
    cudaGetSymbolAddress((void**)&pxs, g_xs);
    cudaGetSymbolAddress((void**)&py, g_y);
    cudaGetSymbolAddress((void**)&pdelta, g_delta);
    cudaGetSymbolAddress((void**)&pdbc, g_dbc);

    // x = embedding[tokens]
    embed_kernel<<<(Mm * Dd) / 256, 256>>>(tokens, embedding, px);

    for (int l = 0; l < NLAYER; l++) {
        // xn = rmsnorm(x, norm_w[l])
        rmsnorm_kernel<<<Mm, 256>>>(px, norm_w + (size_t)l * Dd, pxn);
        // xz = xn @ in_proj_w[l].T     (M, 2*ED)
        launch_sgemm(0, pxn, Dd, in_proj_w + (size_t)l * 2 * ED * Dd, Dd,
                     pxz, 2 * ED, Mm, 2 * ED, Dd, nullptr);
        // xs = silu(conv(xin) + cb)
        conv_silu_kernel<<<(Mm * ED) / 256, 256>>>(pxz, conv_w + (size_t)l * ED * DCONV,
                                                   conv_b + (size_t)l * ED, pxs);
        // dbc = xs @ x_proj_w[l].T     (M, 96)
        launch_sgemm(0, pxs, ED, x_proj_w + (size_t)l * DX * ED, ED,
                     pdbc, DX, Mm, DX, ED, nullptr);
        // delta = softplus(delta_r @ dt_proj_w[l].T + dtb)   (M, ED)
        launch_sgemm(2, pdbc, DX, dt_proj_w + (size_t)l * ED * DR, DR,
                     pdelta, ED, Mm, ED, DR, dt_proj_b + (size_t)l * ED);
        // selective scan -> y (gated, +D*xs)
        scan_kernel<<<(Bb * ED) / 16, 256>>>(pdelta, pxs, pdbc, pxz,
                                             A_log + (size_t)l * ED * Nn,
                                             D_param + (size_t)l * ED, py);
        // x += y @ out_proj_w[l].T   (residual fused in epilogue)
        launch_sgemm(1, py, ED, out_proj_w + (size_t)l * Dd * ED, ED,
                     px, Dd, Mm, Dd, ED, nullptr);
    }

    // final norm + logits = xn @ embedding.T
    rmsnorm_kernel<<<Mm, 256>>>(px, norm_f_w, pxn);
    launch_sgemm(0, pxn, Dd, embedding, Dd, logits, Vv, Mm, Vv, Dd, nullptr);
}

// round 5
// speedup vs baseline: 2.3727x; 2.3727x over previous
#include <cuda_runtime.h>
#include <cuda_fp16.h>
#include <cuda_bf16.h>
#include <math.h>
#include <stdint.h>

// ---------------- problem constants ----------------
#define Vv 32000
#define Dd 1024
#define NLAYER 4
#define ED 2048
#define Nn 16
#define DR 64
#define DCONV 4
#define Bb 2
#define Ll 1024
#define Mm (Bb * Ll)      // 2048 tokens
#define DX (DR + 2 * Nn)  // 96

// ---------------- scratch (no allocs allowed) ----------------
__device__ __align__(256) float g_x[Mm * Dd];
__device__ __align__(256) float g_xz[Mm * 2 * ED];
__device__ __align__(256) float g_xs[Mm * ED];
__device__ __align__(256) float g_delta[Mm * ED];
__device__ __align__(256) float g_dbc[Mm * DX];

// fp16 activation / weight mirrors (zero-initialized; x_proj pad rows stay 0)
__device__ __align__(256) __half h_xn[Mm * Dd];
__device__ __align__(256) __half h_xs[Mm * ED];
__device__ __align__(256) __half h_dr[Mm * DR];
__device__ __align__(256) __half h_y[Mm * ED];
__device__ __align__(256) __half h_w_in[NLAYER * 2 * ED * Dd];
__device__ __align__(256) __half h_w_xp[NLAYER * 128 * ED];   // padded 96->128 rows
__device__ __align__(256) __half h_w_dt[NLAYER * ED * DR];
__device__ __align__(256) __half h_w_out[NLAYER * Dd * ED];
__device__ __align__(256) __half h_emb[Vv * Dd];

// ================= small PTX helpers (all baseline sm_80-era, compile on compute_103) =================
__device__ __forceinline__ uint32_t smem_u32(const void* p) {
    uint32_t a;
    asm("{ .reg .u64 t; cvta.to.shared.u64 t, %1; cvt.u32.u64 %0, t; }" : "=r"(a) : "l"(p));
    return a;
}
__device__ __forceinline__ void ldsm_x4(uint32_t* r, uint32_t addr) {
    asm volatile("ldmatrix.sync.aligned.m8n8.x4.shared.b16 {%0,%1,%2,%3}, [%4];"
                 : "=r"(r[0]), "=r"(r[1]), "=r"(r[2]), "=r"(r[3]) : "r"(addr));
}
__device__ __forceinline__ void mma16816(float* d, const uint32_t* a, uint32_t b0, uint32_t b1) {
    asm volatile("mma.sync.aligned.m16n8k16.row.col.f32.f16.f16.f32 "
                 "{%0,%1,%2,%3}, {%4,%5,%6,%7}, {%8,%9}, {%0,%1,%2,%3};"
                 : "+f"(d[0]), "+f"(d[1]), "+f"(d[2]), "+f"(d[3])
                 : "r"(a[0]), "r"(a[1]), "r"(a[2]), "r"(a[3]), "r"(b0), "r"(b1));
}
#define CP_ASYNC16(dst, src) \
    asm volatile("cp.async.cg.shared.global [%0], [%1], 16;" :: "r"(dst), "l"(src))
#define CP_COMMIT() asm volatile("cp.async.commit_group;" ::: "memory")
#define CP_WAIT2()  asm volatile("cp.async.wait_group 2;" ::: "memory")

// ================= HMMA fp16 GEMM: C(M,N) = A(M,K) @ B(N,K)^T =================
// EPI: 0 store, 1 accumulate into C (residual), 2 softplus(acc + bias[n])
// Block tile 128x128, BK=32, 8 warps (2M x 4N), warp tile 64x32.
// Requires M%128==0, N%128==0 (zero-padded where logical), K%32==0, ldb/lda%8==0.
#define BMt 128
#define BNt 128
#define BKt 32
#define STAGES 4
#define ASTRIDE 40                        // halfs per smem row (32 data + 8 pad)
#define TILE_HALFS (128 * ASTRIDE)        // per operand per stage
#define STAGE_BYTES (2 * TILE_HALFS * 2)  // A + B
#define GEMM_SMEM (STAGES * STAGE_BYTES)  // 81920 B

template <int EPI>
__device__ __forceinline__ void gemm_load_stage(uint32_t sbase, int s,
                                                const __half* A, int lda,
                                                const __half* Bw, int ldb,
                                                int m0, int n0, int c, int tid) {
    uint32_t sa = sbase + s * STAGE_BYTES;
    uint32_t sb = sa + TILE_HALFS * 2;
    const __half* Ap = A + (size_t)m0 * lda + c * BKt;
    const __half* Bp = Bw + (size_t)n0 * ldb + c * BKt;
#pragma unroll
    for (int i = 0; i < 2; i++) {
        int idx = tid + i * 256;          // 0..511
        int row = idx >> 2, slot = idx & 3;
        CP_ASYNC16(sa + (row * ASTRIDE + slot * 8) * 2, Ap + (size_t)row * lda + slot * 8);
        CP_ASYNC16(sb + (row * ASTRIDE + slot * 8) * 2, Bp + (size_t)row * ldb + slot * 8);
    }
}

template <int EPI>
__global__ void __launch_bounds__(256) hgemm_mma(const __half* __restrict__ A, int lda,
                                                 const __half* __restrict__ Bw, int ldb,
                                                 float* __restrict__ C, int ldc,
                                                 int M, int N, int Nstore, int K,
                                                 const float* __restrict__ bias) {
    extern __shared__ __half sh[];
    uint32_t sbase = smem_u32(sh);
    int tid = threadIdx.x;
    int wid = tid >> 5, lane = tid & 31;
    int warp_m = wid >> 2, warp_n = wid & 3;
    int m0 = blockIdx.y * BMt, n0 = blockIdx.x * BNt;
    int KC = K / BKt;

    float acc[4][4][4];
#pragma unroll
    for (int i = 0; i < 4; i++)
#pragma unroll
        for (int j = 0; j < 4; j++)
#pragma unroll
            for (int k = 0; k < 4; k++) acc[i][j][k] = 0.f;

    // prologue: fill STAGES-1 stages
#pragma unroll
    for (int s = 0; s < STAGES - 1; s++) {
        if (s < KC) gemm_load_stage<EPI>(sbase, s, A, lda, Bw, ldb, m0, n0, s, tid);
        CP_COMMIT();
    }

    int lrow = lane & 15;
    int kcol8 = (lane >> 4) * 8;

    for (int c = 0; c < KC; c++) {
        CP_WAIT2();
        __syncthreads();     // chunk c resident; everyone done reading buffer (c-1)%STAGES

        // issue load for chunk c+STAGES-1 into buffer (c-1)%STAGES
        int cn = c + STAGES - 1;
        if (cn < KC)
            gemm_load_stage<EPI>(sbase, cn % STAGES, A, lda, Bw, ldb, m0, n0, cn, tid);
        CP_COMMIT();

        // compute on stage c%STAGES
        uint32_t sa = sbase + (c % STAGES) * STAGE_BYTES;
        uint32_t sb = sa + TILE_HALFS * 2;
#pragma unroll
        for (int kk = 0; kk < 2; kk++) {
            int kof = kk * 16 + kcol8;
            uint32_t afr[4][4], bfr[2][4];
#pragma unroll
            for (int mf = 0; mf < 4; mf++)
                ldsm_x4(afr[mf], sa + ((warp_m * 64 + mf * 16 + lrow) * ASTRIDE + kof) * 2);
#pragma unroll
            for (int nh = 0; nh < 2; nh++)
                ldsm_x4(bfr[nh], sb + ((warp_n * 32 + nh * 16 + lrow) * ASTRIDE + kof) * 2);
#pragma unroll
            for (int mf = 0; mf < 4; mf++)
#pragma unroll
                for (int nf = 0; nf < 4; nf++) {
                    int nh = nf >> 1, odd = nf & 1;
                    mma16816(acc[mf][nf], afr[mf], bfr[nh][odd], bfr[nh][odd + 2]);
                }
        }
        __syncthreads();
    }

    // epilogue: d0,d1 = (row g, cols 2t,2t+1); d2,d3 = row g+8
    int g = lane >> 2, t4 = lane & 3;
#pragma unroll
    for (int mf = 0; mf < 4; mf++) {
        int row0 = m0 + warp_m * 64 + mf * 16 + g;
        float* C0 = C + (size_t)row0 * ldc;
        float* C1 = C0 + (size_t)8 * ldc;
#pragma unroll
        for (int nf = 0; nf < 4; nf++) {
            int n = n0 + warp_n * 32 + nf * 8 + 2 * t4;
            if (n >= Nstore) continue;
            float2 v0 = make_float2(acc[mf][nf][0], acc[mf][nf][1]);
            float2 v1 = make_float2(acc[mf][nf][2], acc[mf][nf][3]);
            if (EPI == 1) {
                float2 o0 = *(float2*)(C0 + n);
                float2 o1 = *(float2*)(C1 + n);
                v0.x += o0.x; v0.y += o0.y;
                v1.x += o1.x; v1.y += o1.y;
            }
            if (EPI == 2) {
                float b0 = bias[n], b1 = bias[n + 1];
                v0.x += b0; v0.y += b1; v1.x += b0; v1.y += b1;
                v0.x = (v0.x > 20.f) ? v0.x : log1pf(expf(v0.x));
                v0.y = (v0.y > 20.f) ? v0.y : log1pf(expf(v0.y));
                v1.x = (v1.x > 20.f) ? v1.x : log1pf(expf(v1.x));
                v1.y = (v1.y > 20.f) ? v1.y : log1pf(expf(v1.y));
            }
            *(float2*)(C0 + n) = v0;
            *(float2*)(C1 + n) = v1;
        }
    }
}

// ================= elementwise / conversion kernels =================
__global__ void __launch_bounds__(256) f32_to_f16_kernel(const float* __restrict__ s,
                                                         __half* __restrict__ d, int n) {
    int i = blockIdx.x * 256 + threadIdx.x;
    if (i < n) d[i] = __float2half(s[i]);
}

// x_proj weights: [NL,96,2048] fp32 -> [NL,128,2048] fp16 (rows 96..127 remain zero)
__global__ void __launch_bounds__(256) xpw_to_f16_kernel(const float* __restrict__ s,
                                                         __half* __restrict__ d) {
    int i = blockIdx.x * 256 + threadIdx.x;
    if (i >= NLAYER * DX * ED) return;
    int l = i / (DX * ED);
    int r = (i / ED) % DX;
    int c = i % ED;
    d[(size_t)l * 128 * ED + (size_t)r * ED + c] = __float2half(s[i]);
}

// extract delta_r (first 64 cols of dbc) -> fp16
__global__ void __launch_bounds__(256) dr_kernel(const float* __restrict__ dbc,
                                                 __half* __restrict__ dr) {
    int i = blockIdx.x * 256 + threadIdx.x;
    int m = i >> 6, j = i & 63;
    dr[i] = __float2half(dbc[m * DX + j]);
}

__global__ void __launch_bounds__(256) embed_kernel(const int* __restrict__ tok,
                                                    const float* __restrict__ emb,
                                                    float* __restrict__ out) {
    int idx = blockIdx.x * 256 + threadIdx.x;
    int m = idx >> 10;
    int d = idx & 1023;
    out[idx] = emb[(size_t)tok[m] * Dd + d];
}

// rmsnorm -> fp16 (only consumed by tensor-core GEMMs)
__global__ void __launch_bounds__(256) rmsnorm_kernel(const float* __restrict__ x,
                                                      const float* __restrict__ w,
                                                      __half* __restrict__ out) {
    int row = blockIdx.x;
    const float* xr = x + (size_t)row * Dd;
    float v[4];
    float s = 0.f;
#pragma unroll
    for (int i = 0; i < 4; i++) {
        v[i] = xr[threadIdx.x + i * 256];
        s += v[i] * v[i];
    }
#pragma unroll
    for (int o = 16; o; o >>= 1) s += __shfl_xor_sync(0xffffffffu, s, o);
    __shared__ float ss[8];
    if ((threadIdx.x & 31) == 0) ss[threadIdx.x >> 5] = s;
    __syncthreads();
    if (threadIdx.x < 32) {
        float t = (threadIdx.x < 8) ? ss[threadIdx.x] : 0.f;
#pragma unroll
        for (int o = 4; o; o >>= 1) t += __shfl_xor_sync(0xffffffffu, t, o);
        if (threadIdx.x == 0) ss[0] = t;
    }
    __syncthreads();
    float r = rsqrtf(ss[0] * (1.f / (float)Dd) + 1e-5f);
    __half* orow = out + (size_t)row * Dd;
#pragma unroll
    for (int i = 0; i < 4; i++) {
        int d = threadIdx.x + i * 256;
        orow[d] = __float2half(v[i] * r * w[d]);
    }
}

// depthwise causal conv + bias + silu; writes fp32 (scan) and fp16 (GEMM)
__global__ void __launch_bounds__(256) conv_silu_kernel(const float* __restrict__ xz,
                                                        const float* __restrict__ cw,
                                                        const float* __restrict__ cb,
                                                        float* __restrict__ xs,
                                                        __half* __restrict__ xs16) {
    int idx = blockIdx.x * 256 + threadIdx.x;
    int e = idx & (ED - 1);
    int m = idx >> 11;
    int l = m & (Ll - 1);
    const float* xin = xz + (size_t)m * (2 * ED) + e;
    float w0 = cw[e * 4 + 0], w1 = cw[e * 4 + 1], w2 = cw[e * 4 + 2], w3 = cw[e * 4 + 3];
    float acc = cb[e] + w3 * xin[0];
    if (l >= 1) acc += w2 * xin[-(2 * ED)];
    if (l >= 2) acc += w1 * xin[-2 * (2 * ED)];
    if (l >= 3) acc += w0 * xin[-3 * (2 * ED)];
    float r = acc / (1.f + __expf(-acc));
    xs[idx] = r;
    xs16[idx] = __float2half(r);
}

// ---------------- selective scan (y written fp16 for out_proj GEMM) ----------------
__global__ void __launch_bounds__(256) scan_kernel(const float* __restrict__ delta,
                                                   const float* __restrict__ xs,
                                                   const float* __restrict__ dbc,
                                                   const float* __restrict__ xz,
                                                   const float* __restrict__ A_log,
                                                   const float* __restrict__ Dp,
                                                   __half* __restrict__ y) {
    int ch = blockIdx.x * 16 + (threadIdx.x >> 4);
    int n = threadIdx.x & 15;
    int b = ch >> 11;
    int e = ch & (ED - 1);
    float a2 = -__expf(A_log[e * Nn + n]) * 1.44269504f;
    float dpar = Dp[e];
    float h = 0.f;
    size_t m0 = (size_t)b * Ll;
    const float* pd = delta + m0 * ED + e;
    const float* pxs = xs + m0 * ED + e;
    const float* pB = dbc + m0 * DX + DR + n;
    const float* pC = dbc + m0 * DX + DR + Nn + n;
    const float* pz = xz + m0 * (2 * ED) + ED + e;
    __half* py = y + m0 * ED + e;

    for (int t = 0; t < Ll; t++) {
        float d = *pd;
        float xv = *pxs;
        float Bn = *pB;
        float Cn = *pC;
        float da = exp2f(d * a2);
        h = fmaf(da, h, d * xv * Bn);
        float p = h * Cn;
        p += __shfl_xor_sync(0xffffffffu, p, 1);
        p += __shfl_xor_sync(0xffffffffu, p, 2);
        p += __shfl_xor_sync(0xffffffffu, p, 4);
        p += __shfl_xor_sync(0xffffffffu, p, 8);
        if (n == 0) {
            float z = *pz;
            float sz = z / (1.f + __expf(-z));
            py[0] = __float2half((p + dpar * xv) * sz);
        }
        pd += ED;
        pxs += ED;
        pB += DX;
        pC += DX;
        pz += 2 * ED;
        py += ED;
    }
}

// ---------------- host side ----------------
static void launch_hgemm(int epi, const __half* A, int lda, const __half* B, int ldb,
                         float* C, int ldc, int M, int N, int Nstore, int K,
                         const float* bias) {
    dim3 grid(N / BNt, M / BMt);
    if (epi == 0) {
        cudaFuncSetAttribute(hgemm_mma<0>, cudaFuncAttributeMaxDynamicSharedMemorySize, GEMM_SMEM);
        hgemm_mma<0><<<grid, 256, GEMM_SMEM>>>(A, lda, B, ldb, C, ldc, M, N, Nstore, K, bias);
    } else if (epi == 1) {
        cudaFuncSetAttribute(hgemm_mma<1>, cudaFuncAttributeMaxDynamicSharedMemorySize, GEMM_SMEM);
        hgemm_mma<1><<<grid, 256, GEMM_SMEM>>>(A, lda, B, ldb, C, ldc, M, N, Nstore, K, bias);
    } else {
        cudaFuncSetAttribute(hgemm_mma<2>, cudaFuncAttributeMaxDynamicSharedMemorySize, GEMM_SMEM);
        hgemm_mma<2><<<grid, 256, GEMM_SMEM>>>(A, lda, B, ldb, C, ldc, M, N, Nstore, K, bias);
    }
}

extern "C" void kernel_launch(void* const* d_in, const int* in_sizes, int n_in,
                              void* d_out, int out_size) {
    const int* tokens = (const int*)d_in[0];
    const float* embedding = (const float*)d_in[1];
    const float* in_proj_w = (const float*)d_in[2];
    const float* conv_w = (const float*)d_in[3];
    const float* conv_b = (const float*)d_in[4];
    const float* x_proj_w = (const float*)d_in[5];
    const float* dt_proj_w = (const float*)d_in[6];
    const float* dt_proj_b = (const float*)d_in[7];
    const float* A_log = (const float*)d_in[8];
    const float* D_param = (const float*)d_in[9];
    const float* out_proj_w = (const float*)d_in[10];
    const float* norm_w = (const float*)d_in[11];
    const float* norm_f_w = (const float*)d_in[12];
    float* logits = (float*)d_out;

    float *px, *pxz, *pxs, *pdelta, *pdbc;
    __half *pxn16, *pxs16, *pdr16, *py16, *pwin, *pwxp, *pwdt, *pwout, *pemb;
    cudaGetSymbolAddress((void**)&px, g_x);
    cudaGetSymbolAddress((void**)&pxz, g_xz);
    cudaGetSymbolAddress((void**)&pxs, g_xs);
    cudaGetSymbolAddress((void**)&pdelta, g_delta);
    cudaGetSymbolAddress((void**)&pdbc, g_dbc);
    cudaGetSymbolAddress((void**)&pxn16, h_xn);
    cudaGetSymbolAddress((void**)&pxs16, h_xs);
    cudaGetSymbolAddress((void**)&pdr16, h_dr);
    cudaGetSymbolAddress((void**)&py16, h_y);
    cudaGetSymbolAddress((void**)&pwin, h_w_in);
    cudaGetSymbolAddress((void**)&pwxp, h_w_xp);
    cudaGetSymbolAddress((void**)&pwdt, h_w_dt);
    cudaGetSymbolAddress((void**)&pwout, h_w_out);
    cudaGetSymbolAddress((void**)&pemb, h_emb);

    // ---- weight conversions fp32 -> fp16 ----
    {
        int n;
        n = NLAYER * 2 * ED * Dd;
        f32_to_f16_kernel<<<(n + 255) / 256, 256>>>(in_proj_w, pwin, n);
        n = NLAYER * ED * DR;
        f32_to_f16_kernel<<<(n + 255) / 256, 256>>>(dt_proj_w, pwdt, n);
        n = NLAYER * Dd * ED;
        f32_to_f16_kernel<<<(n + 255) / 256, 256>>>(out_proj_w, pwout, n);
        n = Vv * Dd;
        f32_to_f16_kernel<<<(n + 255) / 256, 256>>>(embedding, pemb, n);
        n = NLAYER * DX * ED;
        xpw_to_f16_kernel<<<(n + 255) / 256, 256>>>(x_proj_w, pwxp);
    }

    // x = embedding[tokens]
    embed_kernel<<<(Mm * Dd) / 256, 256>>>(tokens, embedding, px);

    for (int l = 0; l < NLAYER; l++) {
        // xn16 = fp16(rmsnorm(x))
        rmsnorm_kernel<<<Mm, 256>>>(px, norm_w + (size_t)l * Dd, pxn16);
        // xz = xn @ in_proj_w[l].T   (2048 x 4096, K=1024)
        launch_hgemm(0, pxn16, Dd, pwin + (size_t)l * 2 * ED * Dd, Dd,
                     pxz, 2 * ED, Mm, 2 * ED, 2 * ED, Dd, nullptr);
        // xs = silu(conv(xin) + cb)  -> fp32 + fp16
        conv_silu_kernel<<<(Mm * ED) / 256, 256>>>(pxz, conv_w + (size_t)l * ED * DCONV,
                                                   conv_b + (size_t)l * ED, pxs, pxs16);
        // dbc = xs @ x_proj_w[l].T   (2048 x 96, padded N=128, K=2048)
        launch_hgemm(0, pxs16, ED, pwxp + (size_t)l * 128 * ED, ED,
                     pdbc, DX, Mm, 128, DX, ED, nullptr);
        // delta_r fp16 extract
        dr_kernel<<<(Mm * DR) / 256, 256>>>(pdbc, pdr16);
        // delta = softplus(delta_r @ dt_proj_w[l].T + dtb)  (2048 x 2048, K=64)
        launch_hgemm(2, pdr16, DR, pwdt + (size_t)l * ED * DR, DR,
                     pdelta, ED, Mm, ED, ED, DR, dt_proj_b + (size_t)l * ED);
        // selective scan -> y fp16 (gated, +D*xs)
        scan_kernel<<<(Bb * ED) / 16, 256>>>(pdelta, pxs, pdbc, pxz,
                                             A_log + (size_t)l * ED * Nn,
                                             D_param + (size_t)l * ED, py16);
        // x += y @ out_proj_w[l].T   (2048 x 1024, K=2048; residual in epilogue)
        launch_hgemm(1, py16, ED, pwout + (size_t)l * Dd * ED, ED,
                     px, Dd, Mm, Dd, Dd, ED, nullptr);
    }

    // final norm + logits = xn @ embedding.T  (2048 x 32000, K=1024)
    rmsnorm_kernel<<<Mm, 256>>>(px, norm_f_w, pxn16);
    launch_hgemm(0, pxn16, Dd, pemb, Dd, logits, Vv, Mm, Vv, Vv, Dd, nullptr);
}

// round 6
// speedup vs baseline: 2.4628x; 1.0380x over previous
#include <cuda_runtime.h>
#include <cuda_fp16.h>
#include <cuda_bf16.h>
#include <math.h>
#include <stdint.h>

// ---------------- problem constants ----------------
#define Vv 32000
#define Dd 1024
#define NLAYER 4
#define ED 2048
#define Nn 16
#define DR 64
#define DCONV 4
#define Bb 2
#define Ll 1024
#define Mm (Bb * Ll)      // 2048 tokens
#define DX (DR + 2 * Nn)  // 96

// ---------------- scratch (no allocs allowed) ----------------
__device__ __align__(256) float g_x[Mm * Dd];
__device__ __align__(256) float g_xz[Mm * 2 * ED];
__device__ __align__(256) float g_xs[Mm * ED];
__device__ __align__(256) float g_delta[Mm * ED];
__device__ __align__(256) float g_dbc[Mm * DX];

// fp16 activation / weight mirrors (zero-initialized; x_proj pad rows stay 0)
__device__ __align__(256) __half h_xn[Mm * Dd];
__device__ __align__(256) __half h_xs[Mm * ED];
__device__ __align__(256) __half h_dr[Mm * DR];
__device__ __align__(256) __half h_y[Mm * ED];
__device__ __align__(256) __half h_w_in[NLAYER * 2 * ED * Dd];
__device__ __align__(256) __half h_w_xp[NLAYER * 128 * ED];   // padded 96->128 rows
__device__ __align__(256) __half h_w_dt[NLAYER * ED * DR];
__device__ __align__(256) __half h_w_out[NLAYER * Dd * ED];
__device__ __align__(256) __half h_emb[Vv * Dd];

// ================= small PTX helpers =================
__device__ __forceinline__ uint32_t smem_u32(const void* p) {
    uint32_t a;
    asm("{ .reg .u64 t; cvta.to.shared.u64 t, %1; cvt.u32.u64 %0, t; }" : "=r"(a) : "l"(p));
    return a;
}
__device__ __forceinline__ void ldsm_x4(uint32_t* r, uint32_t addr) {
    asm volatile("ldmatrix.sync.aligned.m8n8.x4.shared.b16 {%0,%1,%2,%3}, [%4];"
                 : "=r"(r[0]), "=r"(r[1]), "=r"(r[2]), "=r"(r[3]) : "r"(addr));
}
__device__ __forceinline__ void mma16816(float* d, const uint32_t* a, uint32_t b0, uint32_t b1) {
    asm volatile("mma.sync.aligned.m16n8k16.row.col.f32.f16.f16.f32 "
                 "{%0,%1,%2,%3}, {%4,%5,%6,%7}, {%8,%9}, {%0,%1,%2,%3};"
                 : "+f"(d[0]), "+f"(d[1]), "+f"(d[2]), "+f"(d[3])
                 : "r"(a[0]), "r"(a[1]), "r"(a[2]), "r"(a[3]), "r"(b0), "r"(b1));
}
#define CP_ASYNC16(dst, src) \
    asm volatile("cp.async.cg.shared.global [%0], [%1], 16;" :: "r"(dst), "l"(src))
#define CP_COMMIT() asm volatile("cp.async.commit_group;" ::: "memory")
#define CP_WAIT1()  asm volatile("cp.async.wait_group 1;" ::: "memory")

// ================= HMMA fp16 GEMM: C(M,N) = A(M,K) @ B(N,K)^T =================
// EPI: 0 store, 1 accumulate into C (residual), 2 softplus(acc + bias[n]),
//      3 store + fp16 delta_r extract (cols < DR) into aux
// Block tile 128x128, BK=32, 8 warps (2M x 4N), warp tile 64x32.
// 3-stage cp.async pipeline, ONE __syncthreads per chunk, 2 CTAs/SM.
#define BMt 128
#define BNt 128
#define BKt 32
#define STAGES 3
#define ASTRIDE 40                        // halfs per smem row (32 data + 8 pad)
#define TILE_HALFS (128 * ASTRIDE)        // per operand per stage
#define STAGE_BYTES (2 * TILE_HALFS * 2)  // A + B = 20480 B
#define GEMM_SMEM (STAGES * STAGE_BYTES)  // 61440 B

__device__ __forceinline__ void gemm_load_stage(uint32_t sbase, int s,
                                                const __half* A, int lda,
                                                const __half* Bw, int ldb,
                                                int m0, int n0, int c, int tid) {
    uint32_t sa = sbase + s * STAGE_BYTES;
    uint32_t sb = sa + TILE_HALFS * 2;
    const __half* Ap = A + (size_t)m0 * lda + c * BKt;
    const __half* Bp = Bw + (size_t)n0 * ldb + c * BKt;
#pragma unroll
    for (int i = 0; i < 2; i++) {
        int idx = tid + i * 256;          // 0..511
        int row = idx >> 2, slot = idx & 3;
        CP_ASYNC16(sa + (row * ASTRIDE + slot * 8) * 2, Ap + (size_t)row * lda + slot * 8);
        CP_ASYNC16(sb + (row * ASTRIDE + slot * 8) * 2, Bp + (size_t)row * ldb + slot * 8);
    }
}

template <int EPI>
__global__ void __launch_bounds__(256, 2) hgemm_mma(const __half* __restrict__ A, int lda,
                                                    const __half* __restrict__ Bw, int ldb,
                                                    float* __restrict__ C, int ldc,
                                                    int M, int N, int Nstore, int K,
                                                    const float* __restrict__ bias,
                                                    __half* __restrict__ aux) {
    extern __shared__ __half sh[];
    uint32_t sbase = smem_u32(sh);
    int tid = threadIdx.x;
    int wid = tid >> 5, lane = tid & 31;
    int warp_m = wid >> 2, warp_n = wid & 3;
    int m0 = blockIdx.y * BMt, n0 = blockIdx.x * BNt;
    int KC = K / BKt;

    float acc[4][4][4];
#pragma unroll
    for (int i = 0; i < 4; i++)
#pragma unroll
        for (int j = 0; j < 4; j++)
#pragma unroll
            for (int k = 0; k < 4; k++) acc[i][j][k] = 0.f;

    // prologue: fill STAGES-1 stages
#pragma unroll
    for (int s = 0; s < STAGES - 1; s++) {
        if (s < KC) gemm_load_stage(sbase, s, A, lda, Bw, ldb, m0, n0, s, tid);
        CP_COMMIT();
    }

    int lrow = lane & 15;
    int kcol8 = (lane >> 4) * 8;

    for (int c = 0; c < KC; c++) {
        CP_WAIT1();          // chunk c's group done
        __syncthreads();     // all warps finished compute(c-1) -> buf (c-1)%3 reusable

        int cn = c + STAGES - 1;            // load into (c+2)%3 == (c-1)%3
        if (cn < KC)
            gemm_load_stage(sbase, cn % STAGES, A, lda, Bw, ldb, m0, n0, cn, tid);
        CP_COMMIT();

        uint32_t sa = sbase + (c % STAGES) * STAGE_BYTES;
        uint32_t sb = sa + TILE_HALFS * 2;
#pragma unroll
        for (int kk = 0; kk < 2; kk++) {
            int kof = kk * 16 + kcol8;
            uint32_t afr[4][4], bfr[2][4];
#pragma unroll
            for (int mf = 0; mf < 4; mf++)
                ldsm_x4(afr[mf], sa + ((warp_m * 64 + mf * 16 + lrow) * ASTRIDE + kof) * 2);
#pragma unroll
            for (int nh = 0; nh < 2; nh++)
                ldsm_x4(bfr[nh], sb + ((warp_n * 32 + nh * 16 + lrow) * ASTRIDE + kof) * 2);
#pragma unroll
            for (int mf = 0; mf < 4; mf++)
#pragma unroll
                for (int nf = 0; nf < 4; nf++) {
                    int nh = nf >> 1, odd = nf & 1;
                    mma16816(acc[mf][nf], afr[mf], bfr[nh][odd], bfr[nh][odd + 2]);
                }
        }
    }

    // epilogue: d0,d1 = (row g, cols 2t,2t+1); d2,d3 = row g+8
    int g = lane >> 2, t4 = lane & 3;
#pragma unroll
    for (int mf = 0; mf < 4; mf++) {
        int row0 = m0 + warp_m * 64 + mf * 16 + g;
        float* C0 = C + (size_t)row0 * ldc;
        float* C1 = C0 + (size_t)8 * ldc;
#pragma unroll
        for (int nf = 0; nf < 4; nf++) {
            int n = n0 + warp_n * 32 + nf * 8 + 2 * t4;
            if (n >= Nstore) continue;
            float2 v0 = make_float2(acc[mf][nf][0], acc[mf][nf][1]);
            float2 v1 = make_float2(acc[mf][nf][2], acc[mf][nf][3]);
            if (EPI == 1) {
                float2 o0 = *(float2*)(C0 + n);
                float2 o1 = *(float2*)(C1 + n);
                v0.x += o0.x; v0.y += o0.y;
                v1.x += o1.x; v1.y += o1.y;
            }
            if (EPI == 2) {
                float b0 = bias[n], b1 = bias[n + 1];
                v0.x += b0; v0.y += b1; v1.x += b0; v1.y += b1;
                v0.x = (v0.x > 20.f) ? v0.x : log1pf(expf(v0.x));
                v0.y = (v0.y > 20.f) ? v0.y : log1pf(expf(v0.y));
                v1.x = (v1.x > 20.f) ? v1.x : log1pf(expf(v1.x));
                v1.y = (v1.y > 20.f) ? v1.y : log1pf(expf(v1.y));
            }
            *(float2*)(C0 + n) = v0;
            *(float2*)(C1 + n) = v1;
            if (EPI == 3 && n < DR) {   // fp16 delta_r extract (ldc here is DX=96, aux ld is 64)
                __half2* a0 = (__half2*)(aux + (size_t)row0 * DR + n);
                __half2* a1 = (__half2*)(aux + (size_t)(row0 + 8) * DR + n);
                *a0 = __floats2half2_rn(v0.x, v0.y);
                *a1 = __floats2half2_rn(v1.x, v1.y);
            }
        }
    }
}

// ================= elementwise / conversion kernels =================
// vectorized: 8 floats -> 8 halfs per thread
__global__ void __launch_bounds__(256) f32_to_f16_v8(const float* __restrict__ s,
                                                     __half* __restrict__ d, int n8) {
    int i = blockIdx.x * 256 + threadIdx.x;
    if (i >= n8) return;
    const float4* sp = (const float4*)(s) + 2 * i;
    float4 a = sp[0], b = sp[1];
    __half2 h0 = __floats2half2_rn(a.x, a.y);
    __half2 h1 = __floats2half2_rn(a.z, a.w);
    __half2 h2 = __floats2half2_rn(b.x, b.y);
    __half2 h3 = __floats2half2_rn(b.z, b.w);
    uint4 o;
    o.x = *(uint32_t*)&h0; o.y = *(uint32_t*)&h1;
    o.z = *(uint32_t*)&h2; o.w = *(uint32_t*)&h3;
    ((uint4*)d)[i] = o;
}

// x_proj weights: [NL,96,2048] fp32 -> [NL,128,2048] fp16 (rows 96..127 remain zero)
__global__ void __launch_bounds__(256) xpw_to_f16_v8(const float* __restrict__ s,
                                                     __half* __restrict__ d) {
    int i = blockIdx.x * 256 + threadIdx.x;   // over NL*96*2048/8
    if (i >= NLAYER * DX * ED / 8) return;
    int l = i / (DX * ED / 8);
    int rem = i % (DX * ED / 8);
    int r = rem / (ED / 8);
    int cv = rem % (ED / 8);
    const float4* sp = (const float4*)(s + ((size_t)(l * DX + r) * ED)) + 2 * cv;
    float4 a = sp[0], b = sp[1];
    __half2 h0 = __floats2half2_rn(a.x, a.y);
    __half2 h1 = __floats2half2_rn(a.z, a.w);
    __half2 h2 = __floats2half2_rn(b.x, b.y);
    __half2 h3 = __floats2half2_rn(b.z, b.w);
    uint4 o;
    o.x = *(uint32_t*)&h0; o.y = *(uint32_t*)&h1;
    o.z = *(uint32_t*)&h2; o.w = *(uint32_t*)&h3;
    ((uint4*)(d + ((size_t)l * 128 + r) * ED))[cv] = o;
}

__global__ void __launch_bounds__(256) embed_kernel(const int* __restrict__ tok,
                                                    const float* __restrict__ emb,
                                                    float* __restrict__ out) {
    int idx = blockIdx.x * 256 + threadIdx.x;   // over Mm*Dd/4
    int m = idx >> 8;                // Dd/4 = 256 vec4 per row
    int d4 = idx & 255;
    ((float4*)out)[idx] = ((const float4*)(emb + (size_t)tok[m] * Dd))[d4];
}

// rmsnorm -> fp16 (only consumed by tensor-core GEMMs)
__global__ void __launch_bounds__(256) rmsnorm_kernel(const float* __restrict__ x,
                                                      const float* __restrict__ w,
                                                      __half* __restrict__ out) {
    int row = blockIdx.x;
    const float* xr = x + (size_t)row * Dd;
    float v[4];
    float s = 0.f;
#pragma unroll
    for (int i = 0; i < 4; i++) {
        v[i] = xr[threadIdx.x + i * 256];
        s += v[i] * v[i];
    }
#pragma unroll
    for (int o = 16; o; o >>= 1) s += __shfl_xor_sync(0xffffffffu, s, o);
    __shared__ float ss[8];
    if ((threadIdx.x & 31) == 0) ss[threadIdx.x >> 5] = s;
    __syncthreads();
    if (threadIdx.x < 32) {
        float t = (threadIdx.x < 8) ? ss[threadIdx.x] : 0.f;
#pragma unroll
        for (int o = 4; o; o >>= 1) t += __shfl_xor_sync(0xffffffffu, t, o);
        if (threadIdx.x == 0) ss[0] = t;
    }
    __syncthreads();
    float r = rsqrtf(ss[0] * (1.f / (float)Dd) + 1e-5f);
    __half* orow = out + (size_t)row * Dd;
#pragma unroll
    for (int i = 0; i < 4; i++) {
        int d = threadIdx.x + i * 256;
        orow[d] = __float2half(v[i] * r * w[d]);
    }
}

// depthwise causal conv + bias + silu; writes fp32 (scan) and fp16 (GEMM)
__global__ void __launch_bounds__(256) conv_silu_kernel(const float* __restrict__ xz,
                                                        const float* __restrict__ cw,
                                                        const float* __restrict__ cb,
                                                        float* __restrict__ xs,
                                                        __half* __restrict__ xs16) {
    int idx = blockIdx.x * 256 + threadIdx.x;
    int e = idx & (ED - 1);
    int m = idx >> 11;
    int l = m & (Ll - 1);
    const float* xin = xz + (size_t)m * (2 * ED) + e;
    float w0 = cw[e * 4 + 0], w1 = cw[e * 4 + 1], w2 = cw[e * 4 + 2], w3 = cw[e * 4 + 3];
    float acc = cb[e] + w3 * xin[0];
    if (l >= 1) acc += w2 * xin[-(2 * ED)];
    if (l >= 2) acc += w1 * xin[-2 * (2 * ED)];
    if (l >= 3) acc += w0 * xin[-3 * (2 * ED)];
    float r = acc / (1.f + __expf(-acc));
    xs[idx] = r;
    xs16[idx] = __float2half(r);
}

// ---------------- selective scan (y written fp16 for out_proj GEMM) ----------------
__global__ void __launch_bounds__(256) scan_kernel(const float* __restrict__ delta,
                                                   const float* __restrict__ xs,
                                                   const float* __restrict__ dbc,
                                                   const float* __restrict__ xz,
                                                   const float* __restrict__ A_log,
                                                   const float* __restrict__ Dp,
                                                   __half* __restrict__ y) {
    int ch = blockIdx.x * 16 + (threadIdx.x >> 4);
    int n = threadIdx.x & 15;
    int b = ch >> 11;
    int e = ch & (ED - 1);
    float a2 = -__expf(A_log[e * Nn + n]) * 1.44269504f;
    float dpar = Dp[e];
    float h = 0.f;
    size_t m0 = (size_t)b * Ll;
    const float* pd = delta + m0 * ED + e;
    const float* pxs = xs + m0 * ED + e;
    const float* pB = dbc + m0 * DX + DR + n;
    const float* pC = dbc + m0 * DX + DR + Nn + n;
    const float* pz = xz + m0 * (2 * ED) + ED + e;
    __half* py = y + m0 * ED + e;

    for (int t = 0; t < Ll; t++) {
        float d = *pd;
        float xv = *pxs;
        float Bn = *pB;
        float Cn = *pC;
        float da = exp2f(d * a2);
        h = fmaf(da, h, d * xv * Bn);
        float p = h * Cn;
        p += __shfl_xor_sync(0xffffffffu, p, 1);
        p += __shfl_xor_sync(0xffffffffu, p, 2);
        p += __shfl_xor_sync(0xffffffffu, p, 4);
        p += __shfl_xor_sync(0xffffffffu, p, 8);
        if (n == 0) {
            float z = *pz;
            float sz = z / (1.f + __expf(-z));
            py[0] = __float2half((p + dpar * xv) * sz);
        }
        pd += ED;
        pxs += ED;
        pB += DX;
        pC += DX;
        pz += 2 * ED;
        py += ED;
    }
}

// ---------------- host side ----------------
static void launch_hgemm(int epi, const __half* A, int lda, const __half* B, int ldb,
                         float* C, int ldc, int M, int N, int Nstore, int K,
                         const float* bias, __half* aux) {
    dim3 grid(N / BNt, M / BMt);
    if (epi == 0) {
        cudaFuncSetAttribute(hgemm_mma<0>, cudaFuncAttributeMaxDynamicSharedMemorySize, GEMM_SMEM);
        hgemm_mma<0><<<grid, 256, GEMM_SMEM>>>(A, lda, B, ldb, C, ldc, M, N, Nstore, K, bias, aux);
    } else if (epi == 1) {
        cudaFuncSetAttribute(hgemm_mma<1>, cudaFuncAttributeMaxDynamicSharedMemorySize, GEMM_SMEM);
        hgemm_mma<1><<<grid, 256, GEMM_SMEM>>>(A, lda, B, ldb, C, ldc, M, N, Nstore, K, bias, aux);
    } else if (epi == 2) {
        cudaFuncSetAttribute(hgemm_mma<2>, cudaFuncAttributeMaxDynamicSharedMemorySize, GEMM_SMEM);
        hgemm_mma<2><<<grid, 256, GEMM_SMEM>>>(A, lda, B, ldb, C, ldc, M, N, Nstore, K, bias, aux);
    } else {
        cudaFuncSetAttribute(hgemm_mma<3>, cudaFuncAttributeMaxDynamicSharedMemorySize, GEMM_SMEM);
        hgemm_mma<3><<<grid, 256, GEMM_SMEM>>>(A, lda, B, ldb, C, ldc, M, N, Nstore, K, bias, aux);
    }
}

extern "C" void kernel_launch(void* const* d_in, const int* in_sizes, int n_in,
                              void* d_out, int out_size) {
    const int* tokens = (const int*)d_in[0];
    const float* embedding = (const float*)d_in[1];
    const float* in_proj_w = (const float*)d_in[2];
    const float* conv_w = (const float*)d_in[3];
    const float* conv_b = (const float*)d_in[4];
    const float* x_proj_w = (const float*)d_in[5];
    const float* dt_proj_w = (const float*)d_in[6];
    const float* dt_proj_b = (const float*)d_in[7];
    const float* A_log = (const float*)d_in[8];
    const float* D_param = (const float*)d_in[9];
    const float* out_proj_w = (const float*)d_in[10];
    const float* norm_w = (const float*)d_in[11];
    const float* norm_f_w = (const float*)d_in[12];
    float* logits = (float*)d_out;

    float *px, *pxz, *pxs, *pdelta, *pdbc;
    __half *pxn16, *pxs16, *pdr16, *py16, *pwin, *pwxp, *pwdt, *pwout, *pemb;
    cudaGetSymbolAddress((void**)&px, g_x);
    cudaGetSymbolAddress((void**)&pxz, g_xz);
    cudaGetSymbolAddress((void**)&pxs, g_xs);
    cudaGetSymbolAddress((void**)&pdelta, g_delta);
    cudaGetSymbolAddress((void**)&pdbc, g_dbc);
    cudaGetSymbolAddress((void**)&pxn16, h_xn);
    cudaGetSymbolAddress((void**)&pxs16, h_xs);
    cudaGetSymbolAddress((void**)&pdr16, h_dr);
    cudaGetSymbolAddress((void**)&py16, h_y);
    cudaGetSymbolAddress((void**)&pwin, h_w_in);
    cudaGetSymbolAddress((void**)&pwxp, h_w_xp);
    cudaGetSymbolAddress((void**)&pwdt, h_w_dt);
    cudaGetSymbolAddress((void**)&pwout, h_w_out);
    cudaGetSymbolAddress((void**)&pemb, h_emb);

    // ---- weight conversions fp32 -> fp16 (vectorized) ----
    {
        int n8;
        n8 = NLAYER * 2 * ED * Dd / 8;
        f32_to_f16_v8<<<(n8 + 255) / 256, 256>>>(in_proj_w, pwin, n8);
        n8 = NLAYER * ED * DR / 8;
        f32_to_f16_v8<<<(n8 + 255) / 256, 256>>>(dt_proj_w, pwdt, n8);
        n8 = NLAYER * Dd * ED / 8;
        f32_to_f16_v8<<<(n8 + 255) / 256, 256>>>(out_proj_w, pwout, n8);
        n8 = Vv * Dd / 8;
        f32_to_f16_v8<<<(n8 + 255) / 256, 256>>>(embedding, pemb, n8);
        n8 = NLAYER * DX * ED / 8;
        xpw_to_f16_v8<<<(n8 + 255) / 256, 256>>>(x_proj_w, pwxp);
    }

    // x = embedding[tokens]
    embed_kernel<<<(Mm * Dd / 4) / 256, 256>>>(tokens, embedding, px);

    for (int l = 0; l < NLAYER; l++) {
        // xn16 = fp16(rmsnorm(x))
        rmsnorm_kernel<<<Mm, 256>>>(px, norm_w + (size_t)l * Dd, pxn16);
        // xz = xn @ in_proj_w[l].T   (2048 x 4096, K=1024)
        launch_hgemm(0, pxn16, Dd, pwin + (size_t)l * 2 * ED * Dd, Dd,
                     pxz, 2 * ED, Mm, 2 * ED, 2 * ED, Dd, nullptr, nullptr);
        // xs = silu(conv(xin) + cb)  -> fp32 + fp16
        conv_silu_kernel<<<(Mm * ED) / 256, 256>>>(pxz, conv_w + (size_t)l * ED * DCONV,
                                                   conv_b + (size_t)l * ED, pxs, pxs16);
        // dbc = xs @ x_proj_w[l].T   (2048 x 96, padded N=128, K=2048)
        // EPI=3 also extracts delta_r cols fp16 into pdr16
        launch_hgemm(3, pxs16, ED, pwxp + (size_t)l * 128 * ED, ED,
                     pdbc, DX, Mm, 128, DX, ED, nullptr, pdr16);
        // delta = softplus(delta_r @ dt_proj_w[l].T + dtb)  (2048 x 2048, K=64)
        launch_hgemm(2, pdr16, DR, pwdt + (size_t)l * ED * DR, DR,
                     pdelta, ED, Mm, ED, ED, DR, dt_proj_b + (size_t)l * ED, nullptr);
        // selective scan -> y fp16 (gated, +D*xs)
        scan_kernel<<<(Bb * ED) / 16, 256>>>(pdelta, pxs, pdbc, pxz,
                                             A_log + (size_t)l * ED * Nn,
                                             D_param + (size_t)l * ED, py16);
        // x += y @ out_proj_w[l].T   (2048 x 1024, K=2048; residual in epilogue)
        launch_hgemm(1, py16, ED, pwout + (size_t)l * Dd * ED, ED,
                     px, Dd, Mm, Dd, Dd, ED, nullptr, nullptr);
    }

    // final norm + logits = xn @ embedding.T  (2048 x 32000, K=1024)
    rmsnorm_kernel<<<Mm, 256>>>(px, norm_f_w, pxn16);
    launch_hgemm(0, pxn16, Dd, pemb, Dd, logits, Vv, Mm, Vv, Vv, Dd, nullptr, nullptr);
}